// round 1
// baseline (speedup 1.0000x reference)
#include <cuda_runtime.h>
#include <math.h>

#define BB 32
#define TT 256
#define INS 64
#define HH 128
#define G4 (4*HH)        // 512 gate rows
#define TOPK 5
#define EPSV 1e-7f

// ---- device scratch (static allocation only; no cudaMalloc allowed) ----
__device__ float4 g_whp[32*512];          // W_hh packed: [k4][j] -> float4 of W_hh[j][4k4..4k4+3]
__device__ float4 g_wip[16*512];          // W_ih packed: [k4][j]
__device__ float  g_bsum[G4];             // b_ih + b_hh
__device__ float  g_gx[BB*TT*G4];         // precomputed input contributions (16 MB)
__device__ float  g_hold[BB*(TT+1)*HH];   // h_old history buffer (4.2 MB)

// ---------------- pack kernel: transpose weights into coalesced layout ----------------
__global__ void pack_kernel(const float* __restrict__ W_ih,
                            const float* __restrict__ W_hh,
                            const float* __restrict__ b_ih,
                            const float* __restrict__ b_hh) {
    int tid = blockIdx.x * blockDim.x + threadIdx.x;
    int nt  = gridDim.x * blockDim.x;
    float* whp = (float*)g_whp;
    float* wip = (float*)g_wip;
    for (int idx = tid; idx < G4*HH; idx += nt) {
        int j = idx >> 7, k = idx & 127;
        whp[((k >> 2) * 512 + j) * 4 + (k & 3)] = W_hh[idx];
    }
    for (int idx = tid; idx < G4*INS; idx += nt) {
        int j = idx >> 6, k = idx & 63;
        wip[((k >> 2) * 512 + j) * 4 + (k & 3)] = W_ih[idx];
    }
    for (int idx = tid; idx < G4; idx += nt) g_bsum[idx] = b_ih[idx] + b_hh[idx];
}

// ---------------- gx kernel: gx[b][t][j] = b_sum[j] + sum_k W_ih[j][k] x[b][t][k] ----------------
#define TTILE 16
__global__ __launch_bounds__(512) void gx_kernel(const float* __restrict__ x) {
    int b  = blockIdx.x;          // 32
    int t0 = blockIdx.y * TTILE;  // 16 tiles
    int j  = threadIdx.x;         // 512

    __shared__ float xs[TTILE][INS];
    for (int idx = j; idx < TTILE * INS; idx += 512)
        xs[idx >> 6][idx & 63] = x[(b * TT + t0 + (idx >> 6)) * INS + (idx & 63)];

    float4 w[16];
#pragma unroll
    for (int k4 = 0; k4 < 16; k4++) w[k4] = g_wip[k4 * 512 + j];
    float bs = g_bsum[j];
    __syncthreads();

    for (int tt = 0; tt < TTILE; tt++) {
        float acc = bs;
#pragma unroll
        for (int k4 = 0; k4 < 16; k4++) {
            acc = fmaf(w[k4].x, xs[tt][4 * k4 + 0], acc);
            acc = fmaf(w[k4].y, xs[tt][4 * k4 + 1], acc);
            acc = fmaf(w[k4].z, xs[tt][4 * k4 + 2], acc);
            acc = fmaf(w[k4].w, xs[tt][4 * k4 + 3], acc);
        }
        g_gx[(b * TT + t0 + tt) * G4 + j] = acc;
    }
}

__device__ __forceinline__ float sigf(float v) { return 1.0f / (1.0f + expf(-v)); }

// ---------------- recurrent kernel: one block per batch row ----------------
__global__ __launch_bounds__(512) void rec_kernel(const float* __restrict__ w_t,
                                                  float* __restrict__ out) {
    int b    = blockIdx.x;
    int tid  = threadIdx.x;
    int lane = tid & 31;
    int wrp  = tid >> 5;

    __shared__ __align__(16) float h_sh[HH];
    __shared__ float g_sh[G4];
    __shared__ float red[16];
    __shared__ float sb_arr[TT + 1];
    __shared__ float top5v[5];
    __shared__ int   top5i[5];
    __shared__ float wv[5];
    __shared__ int   wi[5];
    __shared__ int   cnt_sh;
    __shared__ float wa_s[HH], wb_s[HH];

    float* out_c = out;            // [B, H] attn_c of last step
    float* out_w = out + BB * HH;  // [B, T] attn_w of last step (sparse)

    float* holdb = g_hold + b * (TT + 1) * HH;
    const float* gxb = g_gx + b * TT * G4;

    if (tid < HH) {
        h_sh[tid]  = 0.0f;
        holdb[tid] = 0.0f;         // h_old row 0 = zeros
        wa_s[tid]  = w_t[tid];
        wb_s[tid]  = w_t[HH + tid];
    }
    if (tid == 0) {
        sb_arr[0] = 0.0f;
        top5v[0] = 0.0f; top5i[0] = 0;
        for (int q = 1; q < 5; q++) { top5v[q] = -1e30f; top5i[q] = 0; }
    }
    for (int r = tid; r < TT; r += 512) out_w[b * TT + r] = 0.0f;

    float c_reg = 0.0f;

    // Cache first half of this thread's W_hh row in registers (64 regs),
    // stream the second half from L1 each step.
    const float4* wp = g_whp;
    float4 wc[16];
#pragma unroll
    for (int k4 = 0; k4 < 16; k4++) wc[k4] = wp[k4 * 512 + tid];

    __syncthreads();

    for (int i = 0; i < TT; i++) {
        // ---- GEMV: g[j] = gx[b][i][j] + sum_k W_hh[j][k] * h[k] ----
        const float4* h4 = (const float4*)h_sh;
        float a0 = 0.f, a1 = 0.f, a2 = 0.f, a3 = 0.f;
#pragma unroll
        for (int k4 = 0; k4 < 16; k4++) {
            float4 w = wc[k4];
            float4 hv = h4[k4];
            if ((k4 & 3) == 0) { a0 = fmaf(w.x,hv.x,a0); a0 = fmaf(w.y,hv.y,a0); a0 = fmaf(w.z,hv.z,a0); a0 = fmaf(w.w,hv.w,a0); }
            else if ((k4 & 3) == 1) { a1 = fmaf(w.x,hv.x,a1); a1 = fmaf(w.y,hv.y,a1); a1 = fmaf(w.z,hv.z,a1); a1 = fmaf(w.w,hv.w,a1); }
            else if ((k4 & 3) == 2) { a2 = fmaf(w.x,hv.x,a2); a2 = fmaf(w.y,hv.y,a2); a2 = fmaf(w.z,hv.z,a2); a2 = fmaf(w.w,hv.w,a2); }
            else { a3 = fmaf(w.x,hv.x,a3); a3 = fmaf(w.y,hv.y,a3); a3 = fmaf(w.z,hv.z,a3); a3 = fmaf(w.w,hv.w,a3); }
        }
#pragma unroll
        for (int k4 = 16; k4 < 32; k4++) {
            float4 w = wp[k4 * 512 + tid];
            float4 hv = h4[k4];
            if ((k4 & 3) == 0) { a0 = fmaf(w.x,hv.x,a0); a0 = fmaf(w.y,hv.y,a0); a0 = fmaf(w.z,hv.z,a0); a0 = fmaf(w.w,hv.w,a0); }
            else if ((k4 & 3) == 1) { a1 = fmaf(w.x,hv.x,a1); a1 = fmaf(w.y,hv.y,a1); a1 = fmaf(w.z,hv.z,a1); a1 = fmaf(w.w,hv.w,a1); }
            else if ((k4 & 3) == 2) { a2 = fmaf(w.x,hv.x,a2); a2 = fmaf(w.y,hv.y,a2); a2 = fmaf(w.z,hv.z,a2); a2 = fmaf(w.w,hv.w,a2); }
            else { a3 = fmaf(w.x,hv.x,a3); a3 = fmaf(w.y,hv.y,a3); a3 = fmaf(w.z,hv.z,a3); a3 = fmaf(w.w,hv.w,a3); }
        }
        g_sh[tid] = gxb[i * G4 + tid] + ((a0 + a1) + (a2 + a3));
        __syncthreads();  // B1: gates ready

        // ---- LSTM cell (threads 0..127, one per h index) ----
        float hl = 0.0f;
        if (tid < HH) {
            float gi = g_sh[tid];
            float gf = g_sh[HH + tid];
            float gg = g_sh[2 * HH + tid];
            float go = g_sh[3 * HH + tid];
            c_reg = sigf(gf) * c_reg + sigf(gi) * tanhf(gg);
            hl = sigf(go) * tanhf(c_reg);
            float pa = tanhf(hl) * wa_s[tid];
#pragma unroll
            for (int off = 16; off; off >>= 1) pa += __shfl_xor_sync(0xffffffffu, pa, off);
            if (lane == 0) red[wrp] = pa;
        }
        __syncthreads();  // B2: ta partials ready

        // ---- sparse attention weights (thread 0) ----
        if (tid == 0) {
            float ta = red[0] + red[1] + red[2] + red[3];
            int rem = i + 1;
            if (rem <= TOPK) {
                for (int r = 0; r < rem; r++) { wv[r] = ta + sb_arr[r]; wi[r] = r; }
                cnt_sh = rem;
            } else {
                float d = top5v[4] + EPSV;
                float ssum = 0.0f;
                int c = 0;
                for (int q = 0; q < 5; q++) {
                    float v = top5v[q] - d;
                    if (v > 0.0f) { wv[c] = v; wi[c] = top5i[q]; ssum += v; c++; }
                }
                float inv = 1.0f / (ssum + EPSV);
                for (int q = 0; q < c; q++) wv[q] *= inv;
                cnt_sh = c;
            }
        }
        __syncthreads();  // B3: weights ready

        // ---- attn_c (<=5 rows of h_old), h_final, new score ----
        if (tid < HH) {
            float ac = 0.0f;
            int cc = cnt_sh;
            for (int q = 0; q < cc; q++) ac = fmaf(wv[q], holdb[wi[q] * HH + tid], ac);
            float hf = hl + ac;
            h_sh[tid] = hf;
            holdb[(i + 1) * HH + tid] = hf;
            float pb = tanhf(hf) * wb_s[tid];
#pragma unroll
            for (int off = 16; off; off >>= 1) pb += __shfl_xor_sync(0xffffffffu, pb, off);
            if (lane == 0) red[wrp] = pb;
            if (i == TT - 1) out_c[b * HH + tid] = ac;
        }
        if (i == TT - 1 && tid == 0) {
            for (int q = 0; q < cnt_sh; q++) out_w[b * TT + wi[q]] = wv[q];
        }
        __syncthreads();  // B4: pb partials ready, h_sh updated

        // ---- running top-5 maintenance (thread 0) ----
        if (tid == 0) {
            float sbn = red[0] + red[1] + red[2] + red[3];
            sb_arr[i + 1] = sbn;
            if (sbn > top5v[4]) {
                int p = 4;
                while (p > 0 && sbn > top5v[p - 1]) {
                    top5v[p] = top5v[p - 1];
                    top5i[p] = top5i[p - 1];
                    p--;
                }
                top5v[p] = sbn;
                top5i[p] = i + 1;
            }
        }
        // next-iteration ordering guaranteed by B1 (writers of red pass it after
        // thread0's read; h_sh protected by B4)
    }
}

extern "C" void kernel_launch(void* const* d_in, const int* in_sizes, int n_in,
                              void* d_out, int out_size) {
    const float* x    = (const float*)d_in[0];
    const float* W_ih = (const float*)d_in[1];
    const float* W_hh = (const float*)d_in[2];
    const float* b_ih = (const float*)d_in[3];
    const float* b_hh = (const float*)d_in[4];
    const float* w_t  = (const float*)d_in[5];
    float* out = (float*)d_out;

    pack_kernel<<<64, 256>>>(W_ih, W_hh, b_ih, b_hh);
    gx_kernel<<<dim3(BB, TT / TTILE), 512>>>(x);
    rec_kernel<<<BB, 512>>>(w_t, out);
}

// round 2
// speedup vs baseline: 1.4499x; 1.4499x over previous
#include <cuda_runtime.h>
#include <math.h>

#define BB 32
#define TT 256
#define INS 64
#define HH 128
#define G4 512
#define EPSV 1e-7f

typedef unsigned long long u64;

// ---- static device scratch (no cudaMalloc allowed) ----
__device__ __align__(16) u64 g_whp[32 * 512 * 2];   // W_hh packed: [k4][j] -> float4 as 2x u64
__device__ float g_gx[BB * TT * G4];                // precomputed input gate contributions

__device__ __forceinline__ u64 ffma2(u64 a, u64 b, u64 c) {
    u64 d;
    asm("fma.rn.f32x2 %0, %1, %2, %3;" : "=l"(d) : "l"(a), "l"(b), "l"(c));
    return d;
}
__device__ __forceinline__ float f2sum(u64 v) {
    float2 f = *reinterpret_cast<float2*>(&v);
    return f.x + f.y;
}
__device__ __forceinline__ float fsig(float x)  { return 1.0f / (1.0f + __expf(-x)); }
__device__ __forceinline__ float ftanh(float x) { return 2.0f / (1.0f + __expf(-2.0f * x)) - 1.0f; }

// ---------------- fused pack + gx kernel ----------------
// blocks (32, 16) x 512 thr. y==0 blocks additionally pack W_hh into g_whp.
__global__ __launch_bounds__(512) void gxpack_kernel(const float* __restrict__ x,
                                                     const float* __restrict__ W_ih,
                                                     const float* __restrict__ W_hh,
                                                     const float* __restrict__ b_ih,
                                                     const float* __restrict__ b_hh) {
    int b = blockIdx.x, ty = blockIdx.y, j = threadIdx.x;

    if (ty == 0) {
        float* whp = (float*)g_whp;
        for (int idx = b * 512 + j; idx < G4 * HH; idx += 32 * 512) {
            int r = idx >> 7, k = idx & 127;
            whp[((k >> 2) * 512 + r) * 4 + (k & 3)] = W_hh[idx];
        }
    }

    __shared__ float xs[16][INS];
    int t0 = ty * 16;
    for (int idx = j; idx < 16 * INS; idx += 512)
        xs[idx >> 6][idx & 63] = x[(b * TT + t0 + (idx >> 6)) * INS + (idx & 63)];

    float4 w[16];
    const float4* wr = (const float4*)(W_ih + j * INS);
#pragma unroll
    for (int k4 = 0; k4 < 16; k4++) w[k4] = wr[k4];
    float bs = b_ih[j] + b_hh[j];
    __syncthreads();

    for (int tt = 0; tt < 16; tt++) {
        float acc = bs;
#pragma unroll
        for (int k4 = 0; k4 < 16; k4++) {
            acc = fmaf(w[k4].x, xs[tt][4 * k4 + 0], acc);
            acc = fmaf(w[k4].y, xs[tt][4 * k4 + 1], acc);
            acc = fmaf(w[k4].z, xs[tt][4 * k4 + 2], acc);
            acc = fmaf(w[k4].w, xs[tt][4 * k4 + 3], acc);
        }
        g_gx[(b * TT + t0 + tt) * G4 + j] = acc;
    }
}

// ---------------- recurrent kernel: one block per batch row ----------------
__global__ __launch_bounds__(512) void rec_kernel(const float* __restrict__ w_t,
                                                  float* __restrict__ out) {
    int b = blockIdx.x, tid = threadIdx.x, lane = tid & 31, wrp = tid >> 5;

    __shared__ __align__(16) float h_sh[HH];
    __shared__ float g_sh[G4];
    __shared__ __align__(16) float slots[5][HH];   // h rows for running top-5
    __shared__ float redA[4], redB[4];
    __shared__ float sb_arr[TT];
    __shared__ float top5v[5];
    __shared__ int   top5r[5];
    __shared__ int   top5s[5];
    __shared__ int   evslot;
    __shared__ float wa_s[HH], wb_s[HH];

    float* out_c = out;             // [B,H]
    float* out_w = out + BB * HH;   // [B,T]
    const float* gxb = g_gx + b * TT * G4;

    if (tid < HH) {
        h_sh[tid] = 0.0f;
        slots[0][tid] = 0.0f;       // row 0 = zeros
        wa_s[tid] = w_t[tid];
        wb_s[tid] = w_t[HH + tid];
    }
    if (tid == 0) {
        sb_arr[0] = 0.0f;
        top5v[0] = 0.0f; top5r[0] = 0; top5s[0] = 0;
        for (int q = 1; q < 5; q++) { top5v[q] = -1e30f; top5r[q] = -1; top5s[q] = q; }
        evslot = -1;
        redB[0] = redB[1] = redB[2] = redB[3] = 0.0f;
    }
    if (tid < TT) out_w[b * TT + tid] = 0.0f;

    float c_reg = 0.0f;

    // cache first half of W_hh row (k=0..63) in registers; stream second half from L1
    const ulonglong2* wp = (const ulonglong2*)g_whp;
    ulonglong2 wc[16];
#pragma unroll
    for (int k4 = 0; k4 < 16; k4++) wc[k4] = wp[k4 * 512 + tid];

    __syncthreads();

    for (int i = 0; i < TT; i++) {
        float gxv = gxb[i * G4 + tid];

        // ---- phase A: top-5 maintenance for row i (thread 0, overlapped with GEMV) ----
        if (tid == 0 && i > 0) {
            float sbn = redB[0] + redB[1] + redB[2] + redB[3];
            sb_arr[i] = sbn;
            if (sbn > top5v[4]) {
                int evs = top5s[4];
                int p = 4;
                while (p > 0 && sbn > top5v[p - 1]) {
                    top5v[p] = top5v[p - 1]; top5r[p] = top5r[p - 1]; top5s[p] = top5s[p - 1];
                    p--;
                }
                top5v[p] = sbn; top5r[p] = i; top5s[p] = evs;
                evslot = evs;
            } else evslot = -1;
        }

        // ---- GEMV with packed f32x2 FMA ----
        const ulonglong2* h2 = (const ulonglong2*)h_sh;
        u64 a0 = 0ull, a1 = 0ull, a2 = 0ull, a3 = 0ull;
#pragma unroll
        for (int k4 = 0; k4 < 16; k4++) {
            ulonglong2 w = wc[k4];
            ulonglong2 hv = h2[k4];
            if (k4 & 1) { a2 = ffma2(w.x, hv.x, a2); a3 = ffma2(w.y, hv.y, a3); }
            else        { a0 = ffma2(w.x, hv.x, a0); a1 = ffma2(w.y, hv.y, a1); }
        }
#pragma unroll
        for (int k4 = 16; k4 < 32; k4++) {
            ulonglong2 w = wp[k4 * 512 + tid];
            ulonglong2 hv = h2[k4];
            if (k4 & 1) { a2 = ffma2(w.x, hv.x, a2); a3 = ffma2(w.y, hv.y, a3); }
            else        { a0 = ffma2(w.x, hv.x, a0); a1 = ffma2(w.y, hv.y, a1); }
        }
        float g = gxv + ((f2sum(a0) + f2sum(a1)) + (f2sum(a2) + f2sum(a3)));
        // gate nonlinearity distributed across all 512 threads (warp-uniform branch)
        g_sh[tid] = ((tid >> 7) == 2) ? ftanh(g) : fsig(g);
        __syncthreads();  // B1

        // ---- phase B: slot copy + LSTM cell + ta partials (threads 0..127) ----
        float hl = 0.0f;
        if (tid < HH) {
            int ev = evslot;
            if (ev >= 0) slots[ev][tid] = h_sh[tid];   // insert row i (prev step's h)
            float ti = g_sh[tid], tf = g_sh[HH + tid];
            float tg = g_sh[2 * HH + tid], to = g_sh[3 * HH + tid];
            c_reg = tf * c_reg + ti * tg;
            hl = to * ftanh(c_reg);
            float pa = ftanh(hl) * wa_s[tid];
#pragma unroll
            for (int o = 16; o; o >>= 1) pa += __shfl_xor_sync(0xffffffffu, pa, o);
            if (lane == 0) redA[wrp] = pa;
        }
        __syncthreads();  // B2

        // ---- phase C: sparse attention (redundant on 128 threads), h update, sb partials ----
        if (tid < HH) {
            float ta = redA[0] + redA[1] + redA[2] + redA[3];
            int rem = i + 1;
            float wv[5]; int ws[5]; int wr[5];
            if (rem <= 5) {
#pragma unroll
                for (int r = 0; r < 5; r++) {
                    if (r < rem) {
                        wv[r] = ta + sb_arr[r];
                        int sl = 0;
#pragma unroll
                        for (int q = 0; q < 5; q++) if (top5r[q] == r) sl = top5s[q];
                        ws[r] = sl; wr[r] = r;
                    } else { wv[r] = 0.0f; ws[r] = 0; wr[r] = 0; }
                }
            } else {
                float d = top5v[4] + EPSV;
                float ssum = 0.0f;
#pragma unroll
                for (int q = 0; q < 5; q++) {
                    float v = fmaxf(top5v[q] - d, 0.0f);
                    wv[q] = v; ws[q] = top5s[q]; wr[q] = top5r[q];
                    ssum += v;
                }
                float inv = 1.0f / (ssum + EPSV);
#pragma unroll
                for (int q = 0; q < 5; q++) wv[q] *= inv;
            }
            float ac = 0.0f;
#pragma unroll
            for (int q = 0; q < 5; q++) ac = fmaf(wv[q], slots[ws[q]][tid], ac);
            float hf = hl + ac;
            h_sh[tid] = hf;
            float pb = ftanh(hf) * wb_s[tid];
#pragma unroll
            for (int o = 16; o; o >>= 1) pb += __shfl_xor_sync(0xffffffffu, pb, o);
            if (lane == 0) redB[wrp] = pb;
            if (i == TT - 1) {
                out_c[b * HH + tid] = ac;
                if (tid == 0) {
#pragma unroll
                    for (int q = 0; q < 5; q++)
                        if (wv[q] != 0.0f) out_w[b * TT + wr[q]] = wv[q];
                }
            }
        }
        __syncthreads();  // B3 (end of step)
    }
}

extern "C" void kernel_launch(void* const* d_in, const int* in_sizes, int n_in,
                              void* d_out, int out_size) {
    const float* x    = (const float*)d_in[0];
    const float* W_ih = (const float*)d_in[1];
    const float* W_hh = (const float*)d_in[2];
    const float* b_ih = (const float*)d_in[3];
    const float* b_hh = (const float*)d_in[4];
    const float* w_t  = (const float*)d_in[5];
    float* out = (float*)d_out;

    gxpack_kernel<<<dim3(BB, TT / 16), 512>>>(x, W_ih, W_hh, b_ih, b_hh);
    rec_kernel<<<BB, 512>>>(w_t, out);
}